// round 10
// baseline (speedup 1.0000x reference)
#include <cuda_runtime.h>
#include <cuda_fp16.h>
#include <cstddef>
#include <cstdint>

#define B_TOTAL 32768
#define T_SEQ   7
#define D_IN    40
#define H_DIM   64
#define FC_DIM  32
#define ROWS    128
#define BLKT    512
#define NBLK    (B_TOTAL / ROWS)   // 256
#define BST     72                 // padded stride in halfs (144 B)

// ---------------- smem byte offsets ----------------
#define SM_BH   0                       // W hi  [256][BST]
#define SM_BL   36864                   // W lo
#define SM_AXH  73728                   // A-x hi [128][BST]
#define SM_AXL  92160                   // A-x lo
#define SM_H0H  110592                  // h buf0 hi [128][BST]
#define SM_H0L  129024
#define SM_H1H  147456                  // h buf1 hi
#define SM_H1L  165888
#define SM_BIAS 184320                  // 256 fp32
#define SM_FC   185344                  // fp32 FC params
#define SM_TOTAL 198656

// phase-A hidden states fp32: [blk][t][128][64]
__device__ __align__(16) float g_scr[(size_t)NBLK * T_SEQ * ROWS * H_DIM];
// precomputed input-gates, per-thread fragment layout: [blk][t][q16][tid512] float4
__device__ __align__(16) float4 g_gx[(size_t)NBLK * T_SEQ * 16 * 512];

// ---------------- helpers ----------------
__device__ __forceinline__ uint32_t smem_u32(const void* p) {
    uint32_t a;
    asm("{ .reg .u64 t; cvta.to.shared.u64 t, %1; cvt.u32.u64 %0, t; }" : "=r"(a) : "l"(p));
    return a;
}
__device__ __forceinline__ void ldsm4(uint32_t r[4], uint32_t addr) {
    asm volatile("ldmatrix.sync.aligned.m8n8.x4.shared.b16 {%0,%1,%2,%3}, [%4];"
        : "=r"(r[0]), "=r"(r[1]), "=r"(r[2]), "=r"(r[3]) : "r"(addr));
}
__device__ __forceinline__ void mma16816(float* c, const uint32_t a[4],
                                         uint32_t b0, uint32_t b1) {
    asm volatile(
        "mma.sync.aligned.m16n8k16.row.col.f32.f16.f16.f32 "
        "{%0,%1,%2,%3}, {%4,%5,%6,%7}, {%8,%9}, {%0,%1,%2,%3};"
        : "+f"(c[0]), "+f"(c[1]), "+f"(c[2]), "+f"(c[3])
        : "r"(a[0]), "r"(a[1]), "r"(a[2]), "r"(a[3]), "r"(b0), "r"(b1));
}
__device__ __forceinline__ float sigf(float x) {
    return __fdividef(1.0f, 1.0f + __expf(-x));
}
__device__ __forceinline__ float tanhf_fast(float x) {
    return __fdividef(2.0f, 1.0f + __expf(-2.0f * x)) - 1.0f;
}
__device__ __forceinline__ void split16(float v, __half& h, __half& l) {
    h = __float2half_rn(v);
    l = __float2half_rn(v - __half2float(h));
}

// ---------------- weight staging: fp32 -> split fp16 [256][BST] ----------------
__device__ void stage_W(const float* __restrict__ W, int K,
                        unsigned char* sm, int tid)
{
    uint4 z = make_uint4(0, 0, 0, 0);
    uint4* zb = (uint4*)(sm + SM_BH);
    for (int i = tid; i < (2 * 36864) / 16; i += BLKT) zb[i] = z;
    __syncthreads();
    for (int e = tid; e < 256 * K; e += BLKT) {
        int c = e / K, k = e % K;
        __half h, l; split16(W[e], h, l);
        uint32_t off = (uint32_t)(c * BST + k) * 2;
        *(__half*)(sm + SM_BH + off) = h;
        *(__half*)(sm + SM_BL + off) = l;
    }
}

// ---------------- 3-term split GEMM over NKS k-chunks ----------------
template <int NKS>
__device__ __forceinline__ void gemm_terms(uint32_t aAh, uint32_t aAl,
                                           uint32_t aBh, uint32_t aBl,
                                           float acc[64])
{
#pragma unroll
    for (int ks = 0; ks < NKS; ks++) {
        const uint32_t kb = (uint32_t)ks * 32;
        uint32_t ah[2][4], al[2][4];
        ldsm4(ah[0], aAh + kb);
        ldsm4(ah[1], aAh + 16 * BST * 2 + kb);
        ldsm4(al[0], aAl + kb);
        ldsm4(al[1], aAl + 16 * BST * 2 + kb);
#pragma unroll
        for (int g4 = 0; g4 < 4; g4++) {
            uint32_t bh[4], bl[4];
            ldsm4(bh, aBh + (uint32_t)g4 * 64 * BST * 2 + kb);
            ldsm4(bl, aBl + (uint32_t)g4 * 64 * BST * 2 + kb);
#pragma unroll
            for (int mt = 0; mt < 2; mt++) {
                float* a0 = &acc[((g4 * 2 + 0) * 2 + mt) * 4];
                float* a1 = &acc[((g4 * 2 + 1) * 2 + mt) * 4];
                mma16816(a0, ah[mt], bh[0], bh[1]);
                mma16816(a1, ah[mt], bh[2], bh[3]);
                mma16816(a0, ah[mt], bl[0], bl[1]);
                mma16816(a1, ah[mt], bl[2], bl[3]);
                mma16816(a0, al[mt], bh[0], bh[1]);
                mma16816(a1, al[mt], bh[2], bh[3]);
            }
        }
    }
}

// ---------------- cell-update epilogue ----------------
template <bool WH, bool WG, bool WFC>
__device__ __forceinline__ void epi(float acc[64], float c[16],
    const float* sBias, unsigned char* sm, int hH, int hL,
    float* __restrict__ gscr, int m0, int j0, int tig, int g8)
{
#pragma unroll
    for (int mt = 0; mt < 2; mt++)
#pragma unroll
    for (int rr = 0; rr < 2; rr++)
#pragma unroll
    for (int nt = 0; nt < 2; nt++) {
        const int jj = j0 + nt * 8 + 2 * tig;
        float2 bi = *(const float2*)(sBias + jj);
        float2 bf = *(const float2*)(sBias + 64 + jj);
        float2 bg = *(const float2*)(sBias + 128 + jj);
        float2 bo = *(const float2*)(sBias + 192 + jj);
        float hv[2];
#pragma unroll
        for (int e = 0; e < 2; e++) {
            float pi = acc[((0 * 2 + nt) * 2 + mt) * 4 + rr * 2 + e] + (e ? bi.y : bi.x);
            float pf = acc[((1 * 2 + nt) * 2 + mt) * 4 + rr * 2 + e] + (e ? bf.y : bf.x);
            float pg = acc[((2 * 2 + nt) * 2 + mt) * 4 + rr * 2 + e] + (e ? bg.y : bg.x);
            float po = acc[((3 * 2 + nt) * 2 + mt) * 4 + rr * 2 + e] + (e ? bo.y : bo.x);
            float ig = sigf(pi), fg = sigf(pf);
            float gg = tanhf_fast(pg), og = sigf(po);
            int ci = ((mt * 2 + rr) * 2 + nt) * 2 + e;
            float cn = fmaf(fg, c[ci], ig * gg);
            c[ci] = cn;
            hv[e] = og * tanhf_fast(cn);
        }
        const int row = m0 + mt * 16 + rr * 8 + g8;
        if (WFC)
            *(float2*)((float*)(sm + SM_AXH) + row * 64 + jj) = make_float2(hv[0], hv[1]);
        if (WH) {
            __half h0, l0, h1, l1;
            split16(hv[0], h0, l0); split16(hv[1], h1, l1);
            uint32_t off = (uint32_t)((row * BST + jj) * 2);
            *(__half2*)(sm + hH + off) = __halves2half2(h0, h1);
            *(__half2*)(sm + hL + off) = __halves2half2(l0, l1);
        }
        if (WG)
            *(float2*)(gscr + row * 64 + jj) = make_float2(hv[0], hv[1]);
    }
}

__global__ void __launch_bounds__(BLKT, 1)
rainfall_lstm_hmma2_kernel(
    const float* __restrict__ x,
    const float* __restrict__ Wih0, const float* __restrict__ Whh0,
    const float* __restrict__ bih0, const float* __restrict__ bhh0,
    const float* __restrict__ Wih1, const float* __restrict__ Whh1,
    const float* __restrict__ bih1, const float* __restrict__ bhh1,
    const float* __restrict__ W1, const float* __restrict__ b1,
    const float* __restrict__ W2, const float* __restrict__ b2,
    float* __restrict__ out)
{
    extern __shared__ unsigned char sm[];
    const uint32_t smb = smem_u32(sm);
    const int tid = threadIdx.x;
    const int w = tid >> 5, lane = tid & 31;
    const int blk = blockIdx.x;
    const int b0 = blk * ROWS;

    const int m0 = (w >> 2) * 32, j0 = (w & 3) * 16;
    const int tig = lane & 3, g8 = lane >> 2;
    const int part = lane >> 3, l = lane & 7;

    const uint32_t aoff =
        (uint32_t)(((m0 + (part & 1) * 8 + l) * BST + (part >> 1) * 8) * 2);
    const uint32_t boff =
        (uint32_t)(((j0 + (part >> 1) * 8 + l) * BST + (part & 1) * 8) * 2);
    const uint32_t aBh = smb + SM_BH + boff;
    const uint32_t aBl = smb + SM_BL + boff;
    const float* sBias = (const float*)(sm + SM_BIAS);

    // ======== PHASE A ========
    stage_W(Wih0, D_IN, sm, tid);
    {   // zero A-x (pad cols)
        uint4 z = make_uint4(0, 0, 0, 0);
        uint4* za = (uint4*)(sm + SM_AXH);
        for (int i = tid; i < (2 * 18432) / 16; i += BLKT) za[i] = z;
    }
    __syncthreads();

    // --- precompute gx0[t] = x_t @ Wih0^T (bulk, no recurrence) ---
    for (int t = 0; t < T_SEQ; t++) {
        {   // stage x_t (rows 0..127, cols 0..39)
            int row = tid >> 2, q4 = tid & 3;
            const float2* xb = (const float2*)(
                x + ((size_t)(b0 + row) * T_SEQ + t) * D_IN + q4 * 10);
#pragma unroll
            for (int i = 0; i < 5; i++) {
                float2 v = xb[i];
                __half h0, l0, h1, l1;
                split16(v.x, h0, l0); split16(v.y, h1, l1);
                uint32_t off = (uint32_t)((row * BST + q4 * 10 + 2 * i) * 2);
                *(__half2*)(sm + SM_AXH + off) = __halves2half2(h0, h1);
                *(__half2*)(sm + SM_AXL + off) = __halves2half2(l0, l1);
            }
        }
        __syncthreads();
        float acc[64];
#pragma unroll
        for (int i = 0; i < 64; i++) acc[i] = 0.0f;
        gemm_terms<3>(smb + SM_AXH + aoff, smb + SM_AXL + aoff, aBh, aBl, acc);
        float4* gg = g_gx + (size_t)(blk * T_SEQ + t) * 16 * 512;
#pragma unroll
        for (int q = 0; q < 16; q++)
            gg[q * 512 + tid] = make_float4(acc[4*q], acc[4*q+1], acc[4*q+2], acc[4*q+3]);
        __syncthreads();
    }

    // --- recurrent loop, layer 0 ---
    stage_W(Whh0, H_DIM, sm, tid);
    {
        float* sB = (float*)(sm + SM_BIAS);
        for (int i = tid; i < 256; i += BLKT) sB[i] = bih0[i] + bhh0[i];
        uint4 z = make_uint4(0, 0, 0, 0);
        uint4* zh = (uint4*)(sm + SM_H0H);
        for (int i = tid; i < (2 * 18432) / 16; i += BLKT) zh[i] = z;   // buf0 hi+lo
    }
    __syncthreads();

    float c[16];
#pragma unroll
    for (int i = 0; i < 16; i++) c[i] = 0.0f;
    for (int t = 0; t < T_SEQ; t++) {
        const float4* gg = g_gx + (size_t)(blk * T_SEQ + t) * 16 * 512;
        float acc[64];
#pragma unroll
        for (int q = 0; q < 16; q++) {
            float4 v = gg[q * 512 + tid];
            acc[4*q] = v.x; acc[4*q+1] = v.y; acc[4*q+2] = v.z; acc[4*q+3] = v.w;
        }
        const int rH = (t & 1) ? SM_H1H : SM_H0H, rL = (t & 1) ? SM_H1L : SM_H0L;
        const int wH = (t & 1) ? SM_H0H : SM_H1H, wL = (t & 1) ? SM_H0L : SM_H1L;
        gemm_terms<4>(smb + rH + aoff, smb + rL + aoff, aBh, aBl, acc);
        epi<true, true, false>(acc, c, sBias, sm, wH, wL,
            g_scr + ((size_t)blk * T_SEQ + t) * (ROWS * H_DIM),
            m0, j0, tig, g8);
        __syncthreads();
    }

    // ======== PHASE B ========
    stage_W(Wih1, H_DIM, sm, tid);
    {   // FC params
        float* fw = (float*)(sm + SM_FC);
        for (int i = tid; i < FC_DIM * H_DIM; i += BLKT) fw[i] = W1[i];
        if (tid < FC_DIM) { fw[2048 + tid] = b1[tid]; fw[2080 + tid] = W2[tid]; }
        if (tid == 0) fw[2112] = b2[0];
    }
    __syncthreads();

    // --- precompute gx1[t] = h1_t @ Wih1^T ---
    for (int t = 0; t < T_SEQ; t++) {
        {
            const float2* src = (const float2*)(
                g_scr + ((size_t)blk * T_SEQ + t) * (ROWS * H_DIM));
#pragma unroll
            for (int i = 0; i < 8; i++) {
                int fi = tid + i * BLKT;
                int row = fi >> 5, jp = fi & 31;
                float2 v = src[fi];
                __half h0, l0, h1, l1;
                split16(v.x, h0, l0); split16(v.y, h1, l1);
                uint32_t off = (uint32_t)((row * BST + 2 * jp) * 2);
                *(__half2*)(sm + SM_AXH + off) = __halves2half2(h0, h1);
                *(__half2*)(sm + SM_AXL + off) = __halves2half2(l0, l1);
            }
        }
        __syncthreads();
        float acc[64];
#pragma unroll
        for (int i = 0; i < 64; i++) acc[i] = 0.0f;
        gemm_terms<4>(smb + SM_AXH + aoff, smb + SM_AXL + aoff, aBh, aBl, acc);
        float4* gg = g_gx + (size_t)(blk * T_SEQ + t) * 16 * 512;
#pragma unroll
        for (int q = 0; q < 16; q++)
            gg[q * 512 + tid] = make_float4(acc[4*q], acc[4*q+1], acc[4*q+2], acc[4*q+3]);
        __syncthreads();
    }

    // --- recurrent loop, layer 1 ---
    stage_W(Whh1, H_DIM, sm, tid);
    {
        float* sB = (float*)(sm + SM_BIAS);
        for (int i = tid; i < 256; i += BLKT) sB[i] = bih1[i] + bhh1[i];
        uint4 z = make_uint4(0, 0, 0, 0);
        uint4* zh = (uint4*)(sm + SM_H0H);
        for (int i = tid; i < (2 * 18432) / 16; i += BLKT) zh[i] = z;
    }
    __syncthreads();

#pragma unroll
    for (int i = 0; i < 16; i++) c[i] = 0.0f;
    for (int t = 0; t < T_SEQ; t++) {
        const float4* gg = g_gx + (size_t)(blk * T_SEQ + t) * 16 * 512;
        float acc[64];
#pragma unroll
        for (int q = 0; q < 16; q++) {
            float4 v = gg[q * 512 + tid];
            acc[4*q] = v.x; acc[4*q+1] = v.y; acc[4*q+2] = v.z; acc[4*q+3] = v.w;
        }
        const int rH = (t & 1) ? SM_H1H : SM_H0H, rL = (t & 1) ? SM_H1L : SM_H0L;
        const int wH = (t & 1) ? SM_H0H : SM_H1H, wL = (t & 1) ? SM_H0L : SM_H1L;
        gemm_terms<4>(smb + rH + aoff, smb + rL + aoff, aBh, aBl, acc);
        if (t < T_SEQ - 1)
            epi<true, false, false>(acc, c, sBias, sm, wH, wL, nullptr, m0, j0, tig, g8);
        else
            epi<false, false, true>(acc, c, sBias, sm, wH, wL, nullptr, m0, j0, tig, g8);
        __syncthreads();
    }

    // ---- FC head: one thread per row ----
    if (tid < ROWS) {
        const float* sFC = (const float*)(sm + SM_AXH);
        const float* fw = (const float*)(sm + SM_FC);
        float hv[H_DIM];
#pragma unroll
        for (int j = 0; j < H_DIM; j++) hv[j] = sFC[tid * 64 + j];
        float o = fw[2112];
#pragma unroll
        for (int r = 0; r < FC_DIM; r++) {
            float a = fw[2048 + r];
            const float* wr = fw + r * H_DIM;
#pragma unroll
            for (int j = 0; j < H_DIM; j++) a = fmaf(hv[j], wr[j], a);
            o = fmaf(fmaxf(a, 0.0f), fw[2080 + r], o);
        }
        out[b0 + tid] = o;
    }
}

extern "C" void kernel_launch(void* const* d_in, const int* in_sizes, int n_in,
                              void* d_out, int out_size)
{
    (void)in_sizes; (void)n_in; (void)out_size;
    const float* x    = (const float*)d_in[0];
    const float* Wih0 = (const float*)d_in[1];
    const float* Whh0 = (const float*)d_in[2];
    const float* bih0 = (const float*)d_in[3];
    const float* bhh0 = (const float*)d_in[4];
    const float* Wih1 = (const float*)d_in[5];
    const float* Whh1 = (const float*)d_in[6];
    const float* bih1 = (const float*)d_in[7];
    const float* bhh1 = (const float*)d_in[8];
    const float* W1   = (const float*)d_in[9];
    const float* b1   = (const float*)d_in[10];
    const float* W2   = (const float*)d_in[11];
    const float* b2   = (const float*)d_in[12];
    float* out = (float*)d_out;

    cudaFuncSetAttribute(rainfall_lstm_hmma2_kernel,
                         cudaFuncAttributeMaxDynamicSharedMemorySize,
                         SM_TOTAL);

    rainfall_lstm_hmma2_kernel<<<NBLK, BLKT, SM_TOTAL>>>(
        x, Wih0, Whh0, bih0, bhh0, Wih1, Whh1, bih1, bhh1,
        W1, b1, W2, b2, out);
}

// round 11
// speedup vs baseline: 1.7198x; 1.7198x over previous
#include <cuda_runtime.h>
#include <cuda_fp16.h>
#include <cstddef>
#include <cstdint>

#define B_TOTAL 32768
#define T_SEQ   7
#define D_IN    40
#define H_DIM   64
#define FC_DIM  32
#define ROWS    128
#define BLKT    512
#define NBLK    (B_TOTAL / ROWS)   // 256
#define AST     136                // padded stride in halfs (272 B)

// ---------------- smem byte offsets ----------------
#define SM_A0H  0                       // A buf0 hi [128][AST] halfs
#define SM_A1H  34816                   // A buf1 hi
#define SM_BH   69632                   // W hi  [256][AST] halfs
#define SM_BL   139264                  // W lo
#define SM_BIAS 208896                  // 256 fp32
#define SM_FC   209920                  // FC weights fp32
#define SM_TOTAL 218372

// phase-A hidden states fp32: [blk][t][128][64]
__device__ __align__(16) float g_scr[(size_t)NBLK * T_SEQ * ROWS * H_DIM];

// ---------------- helpers ----------------
__device__ __forceinline__ uint32_t smem_u32(const void* p) {
    uint32_t a;
    asm("{ .reg .u64 t; cvta.to.shared.u64 t, %1; cvt.u32.u64 %0, t; }" : "=r"(a) : "l"(p));
    return a;
}
__device__ __forceinline__ void ldsm4(uint32_t r[4], uint32_t addr) {
    asm volatile("ldmatrix.sync.aligned.m8n8.x4.shared.b16 {%0,%1,%2,%3}, [%4];"
        : "=r"(r[0]), "=r"(r[1]), "=r"(r[2]), "=r"(r[3]) : "r"(addr));
}
__device__ __forceinline__ void mma16816(float* c, const uint32_t a[4],
                                         uint32_t b0, uint32_t b1) {
    asm volatile(
        "mma.sync.aligned.m16n8k16.row.col.f32.f16.f16.f32 "
        "{%0,%1,%2,%3}, {%4,%5,%6,%7}, {%8,%9}, {%0,%1,%2,%3};"
        : "+f"(c[0]), "+f"(c[1]), "+f"(c[2]), "+f"(c[3])
        : "r"(a[0]), "r"(a[1]), "r"(a[2]), "r"(a[3]), "r"(b0), "r"(b1));
}
__device__ __forceinline__ float sigf(float x) {
    return __fdividef(1.0f, 1.0f + __expf(-x));
}
__device__ __forceinline__ float tanhf_fast(float x) {
    return __fdividef(2.0f, 1.0f + __expf(-2.0f * x)) - 1.0f;
}
__device__ __forceinline__ void split16(float v, __half& h, __half& l) {
    h = __float2half_rn(v);
    l = __float2half_rn(v - __half2float(h));
}

// ---------------- weight staging: fp32 -> split fp16 [256][AST] ----------------
// cols [0,Kx) = W_in, cols [64,128) = W_hh (combined A-tile K layout)
__device__ void stage_weights(const float* __restrict__ Wx, int Kx,
                              const float* __restrict__ Wh,
                              const float* __restrict__ bi, const float* __restrict__ bh,
                              unsigned char* sm, int tid)
{
    uint4 z = make_uint4(0, 0, 0, 0);
    uint4* zb = (uint4*)(sm + SM_BH);
    for (int i = tid; i < (2 * 69632) / 16; i += BLKT) zb[i] = z;
    __syncthreads();

    for (int e = tid; e < 256 * Kx; e += BLKT) {
        int c = e / Kx, k = e % Kx;
        __half h, l; split16(Wx[e], h, l);
        uint32_t off = (uint32_t)(c * AST + k) * 2;
        *(__half*)(sm + SM_BH + off) = h;
        *(__half*)(sm + SM_BL + off) = l;
    }
    for (int e = tid; e < 256 * H_DIM; e += BLKT) {
        int c = e / H_DIM, k = e % H_DIM;
        __half h, l; split16(Wh[e], h, l);
        uint32_t off = (uint32_t)(c * AST + 64 + k) * 2;
        *(__half*)(sm + SM_BH + off) = h;
        *(__half*)(sm + SM_BL + off) = l;
    }
    float* sB = (float*)(sm + SM_BIAS);
    for (int i = tid; i < 256; i += BLKT) sB[i] = bi[i] + bh[i];
}

// ---------------- one LSTM layer (7 steps), one sync per step ----------------
template <bool PA>
__device__ void run_phase(unsigned char* sm, uint32_t smb,
                          const float* __restrict__ x, int b0, int blk, int tid)
{
    const int w = tid >> 5, lane = tid & 31;
    const int m0 = (w >> 2) * 32, j0 = (w & 3) * 16;
    const int tig = lane & 3, g8 = lane >> 2;
    const int part = lane >> 3, l = lane & 7;

    const uint32_t aoff =
        (uint32_t)(((m0 + (part & 1) * 8 + l) * AST + (part >> 1) * 8) * 2);
    const uint32_t boff =
        (uint32_t)(((j0 + (part >> 1) * 8 + l) * AST + (part & 1) * 8) * 2);
    const uint32_t aBh = smb + SM_BH + boff;
    const uint32_t aBl = smb + SM_BL + boff;
    const uint32_t aAbuf[2] = { smb + SM_A0H + aoff, smb + SM_A1H + aoff };
    const float* sBias = (const float*)(sm + SM_BIAS);

    float acc[64];
    float c[16];
#pragma unroll
    for (int i = 0; i < 16; i++) c[i] = 0.0f;

    for (int t = 0; t < T_SEQ; t++) {
        unsigned char* bufR = sm + ((t & 1) ? SM_A1H : SM_A0H);       // MMA reads
        unsigned char* bufW = sm + ((t & 1) ? SM_A0H : SM_A1H);       // epi writes h_t

        // ---- stage x_t into the READ buffer (h_{t-1} already there) ----
        if (PA) {
            int row = tid >> 2, q4 = tid & 3;   // 10 floats each
            const float2* xb = (const float2*)(
                x + ((size_t)(b0 + row) * T_SEQ + t) * D_IN + q4 * 10);
#pragma unroll
            for (int i = 0; i < 5; i++) {
                float2 v = xb[i];
                uint32_t off = (uint32_t)((row * AST + q4 * 10 + 2 * i) * 2);
                *(__half2*)(bufR + off) =
                    __halves2half2(__float2half_rn(v.x), __float2half_rn(v.y));
            }
        } else {
            const float2* src = (const float2*)(
                g_scr + ((size_t)blk * T_SEQ + t) * (ROWS * H_DIM));
#pragma unroll
            for (int i = 0; i < 8; i++) {
                int fi = tid + i * BLKT;           // 0..4095 float2
                int row = fi >> 5, jp = fi & 31;
                float2 v = src[fi];
                uint32_t off = (uint32_t)((row * AST + 2 * jp) * 2);
                *(__half2*)(bufR + off) =
                    __halves2half2(__float2half_rn(v.x), __float2half_rn(v.y));
            }
        }
        __syncthreads();   // the ONLY barrier per step

        // ---- 2-term GEMM: acc = Ah@Bh + Ah@Bl ----
        const uint32_t aAh = aAbuf[t & 1];
#pragma unroll
        for (int i = 0; i < 64; i++) acc[i] = 0.0f;
#pragma unroll
        for (int ks = 0; ks < 8; ks++) {
            if (PA && ks == 3) continue;       // cols 48..63 are zero pad
            const uint32_t kb = (uint32_t)ks * 32;   // 16 halfs = 32 B
            uint32_t ah[2][4];
            ldsm4(ah[0], aAh + kb);
            ldsm4(ah[1], aAh + 16 * AST * 2 + kb);
#pragma unroll
            for (int g4 = 0; g4 < 4; g4++) {
                uint32_t bh[4], bl[4];
                ldsm4(bh, aBh + (uint32_t)g4 * 64 * AST * 2 + kb);
                ldsm4(bl, aBl + (uint32_t)g4 * 64 * AST * 2 + kb);
#pragma unroll
                for (int mt = 0; mt < 2; mt++) {
                    float* a0 = &acc[((g4 * 2 + 0) * 2 + mt) * 4];
                    float* a1 = &acc[((g4 * 2 + 1) * 2 + mt) * 4];
                    mma16816(a0, ah[mt], bh[0], bh[1]);
                    mma16816(a1, ah[mt], bh[2], bh[3]);
                    mma16816(a0, ah[mt], bl[0], bl[1]);
                    mma16816(a1, ah[mt], bl[2], bl[3]);
                }
            }
        }

        // ---- epilogue: gates -> c, h_t -> WRITE buffer (no barrier needed) ----
        const bool last = (!PA) && (t == T_SEQ - 1);
        float* gscr = PA ? g_scr + ((size_t)blk * T_SEQ + t) * (ROWS * H_DIM) : nullptr;
#pragma unroll
        for (int mt = 0; mt < 2; mt++)
#pragma unroll
        for (int rr = 0; rr < 2; rr++)
#pragma unroll
        for (int nt = 0; nt < 2; nt++) {
            const int jj = j0 + nt * 8 + 2 * tig;
            float2 bi = *(const float2*)(sBias + jj);
            float2 bf = *(const float2*)(sBias + 64 + jj);
            float2 bg = *(const float2*)(sBias + 128 + jj);
            float2 bo = *(const float2*)(sBias + 192 + jj);
            float hv[2];
#pragma unroll
            for (int e = 0; e < 2; e++) {
                float pi = acc[((0 * 2 + nt) * 2 + mt) * 4 + rr * 2 + e] + (e ? bi.y : bi.x);
                float pf = acc[((1 * 2 + nt) * 2 + mt) * 4 + rr * 2 + e] + (e ? bf.y : bf.x);
                float pg = acc[((2 * 2 + nt) * 2 + mt) * 4 + rr * 2 + e] + (e ? bg.y : bg.x);
                float po = acc[((3 * 2 + nt) * 2 + mt) * 4 + rr * 2 + e] + (e ? bo.y : bo.x);
                float ig = sigf(pi), fg = sigf(pf);
                float gg = tanhf_fast(pg), og = sigf(po);
                int ci = ((mt * 2 + rr) * 2 + nt) * 2 + e;
                float cn = fmaf(fg, c[ci], ig * gg);
                c[ci] = cn;
                hv[e] = og * tanhf_fast(cn);
            }
            const int row = m0 + mt * 16 + rr * 8 + g8;
            if (last) {
                // final h2 as fp32 into buf1 region (write buffer at t=6)
                *(float2*)((float*)(sm + SM_A1H) + row * 64 + jj) =
                    make_float2(hv[0], hv[1]);
            } else {
                uint32_t off = (uint32_t)((row * AST + 64 + jj) * 2);
                *(__half2*)(bufW + off) =
                    __halves2half2(__float2half_rn(hv[0]), __float2half_rn(hv[1]));
                if (PA)
                    *(float2*)(gscr + row * 64 + jj) = make_float2(hv[0], hv[1]);
            }
        }
        // next iteration: x staging targets bufW, then the single sync orders
        // all bufW writes before its ldsm reads.
    }
}

__global__ void __launch_bounds__(BLKT, 1)
rainfall_lstm_hmma3_kernel(
    const float* __restrict__ x,
    const float* __restrict__ Wih0, const float* __restrict__ Whh0,
    const float* __restrict__ bih0, const float* __restrict__ bhh0,
    const float* __restrict__ Wih1, const float* __restrict__ Whh1,
    const float* __restrict__ bih1, const float* __restrict__ bhh1,
    const float* __restrict__ W1, const float* __restrict__ b1,
    const float* __restrict__ W2, const float* __restrict__ b2,
    float* __restrict__ out)
{
    extern __shared__ unsigned char sm[];
    const uint32_t smb = smem_u32(sm);
    const int tid = threadIdx.x;
    const int blk = blockIdx.x;
    const int b0 = blk * ROWS;

    // ---- phase A setup ----
    stage_weights(Wih0, D_IN, Whh0, bih0, bhh0, sm, tid);
    {   // zero both A buffers (x pad cols 40..63 stay 0 forever; h0 = 0)
        uint4 z = make_uint4(0, 0, 0, 0);
        uint4* za = (uint4*)(sm + SM_A0H);
        for (int i = tid; i < (2 * 34816) / 16; i += BLKT) za[i] = z;
    }
    __syncthreads();
    run_phase<true>(sm, smb, x, b0, blk, tid);
    __syncthreads();   // phase-A writes done before W restage

    // ---- phase B setup ----
    stage_weights(Wih1, H_DIM, Whh1, bih1, bhh1, sm, tid);
    {   // zero both A buffers (h0 = 0 for layer 1)
        uint4 z = make_uint4(0, 0, 0, 0);
        uint4* za = (uint4*)(sm + SM_A0H);
        for (int i = tid; i < (2 * 34816) / 16; i += BLKT) za[i] = z;
    }
    {   // FC weights
        float* fw = (float*)(sm + SM_FC);
        for (int i = tid; i < FC_DIM * H_DIM; i += BLKT) fw[i] = W1[i];
        if (tid < FC_DIM) { fw[2048 + tid] = b1[tid]; fw[2080 + tid] = W2[tid]; }
        if (tid == 0) fw[2112] = b2[0];
    }
    __syncthreads();
    run_phase<false>(sm, smb, nullptr, b0, blk, tid);
    __syncthreads();   // final fp32 h2 (in SM_A1H) complete

    // ---- FC head: one thread per row ----
    if (tid < ROWS) {
        const float* sFC = (const float*)(sm + SM_A1H);
        const float* fw = (const float*)(sm + SM_FC);
        float hv[H_DIM];
#pragma unroll
        for (int j = 0; j < H_DIM; j++) hv[j] = sFC[tid * 64 + j];
        float o = fw[2112];
#pragma unroll
        for (int r = 0; r < FC_DIM; r++) {
            float a = fw[2048 + r];
            const float* wr = fw + r * H_DIM;
#pragma unroll
            for (int j = 0; j < H_DIM; j++) a = fmaf(hv[j], wr[j], a);
            o = fmaf(fmaxf(a, 0.0f), fw[2080 + r], o);
        }
        out[b0 + tid] = o;
    }
}

extern "C" void kernel_launch(void* const* d_in, const int* in_sizes, int n_in,
                              void* d_out, int out_size)
{
    (void)in_sizes; (void)n_in; (void)out_size;
    const float* x    = (const float*)d_in[0];
    const float* Wih0 = (const float*)d_in[1];
    const float* Whh0 = (const float*)d_in[2];
    const float* bih0 = (const float*)d_in[3];
    const float* bhh0 = (const float*)d_in[4];
    const float* Wih1 = (const float*)d_in[5];
    const float* Whh1 = (const float*)d_in[6];
    const float* bih1 = (const float*)d_in[7];
    const float* bhh1 = (const float*)d_in[8];
    const float* W1   = (const float*)d_in[9];
    const float* b1   = (const float*)d_in[10];
    const float* W2   = (const float*)d_in[11];
    const float* b2   = (const float*)d_in[12];
    float* out = (float*)d_out;

    cudaFuncSetAttribute(rainfall_lstm_hmma3_kernel,
                         cudaFuncAttributeMaxDynamicSharedMemorySize,
                         SM_TOTAL);

    rainfall_lstm_hmma3_kernel<<<NBLK, BLKT, SM_TOTAL>>>(
        x, Wih0, Whh0, bih0, bhh0, Wih1, Whh1, bih1, bhh1,
        W1, b1, W2, b2, out);
}